// round 17
// baseline (speedup 1.0000x reference)
#include <cuda_runtime.h>
#include <cuda_fp16.h>
#include <cstdint>

#define NT 4096
#define D  128
#define H  8
#define BN 64
#define NB (NT / BN)
#define SPLITK 4
#define NBH (NB / SPLITK)     // 16 key blocks per quarter
#define NTILES 2048           // 64 q-tiles x 8 heads x 4 key-quarters
#define PGRID 456             // 3 CTAs/SM x 152 SMs

// ---------------- scratch globals ---------------------------------------------
__device__ __align__(16) __half g_qh[H * NT * D];
__device__ __align__(16) __half g_kh[H * NT * D];
__device__ __align__(16) __half g_vh[H * D * NT];   // transposed [h][d][n]
__device__ __align__(16) float  g_po[SPLITK][H * NT * D]; // unnormalized partial O
__device__ float g_pm[SPLITK][H * NT];                    // partial row max
__device__ float g_pl[SPLITK][H * NT];                    // partial row sum
__device__ __align__(16) float  g_o[H * NT * D];
__device__ float g_wgT[D * D];
__device__ unsigned int g_ctr;

__device__ __align__(16) __half g_xh[NT * D];
__device__ __align__(16) __half g_xl[NT * D];
__device__ __align__(16) __half g_wT[3][2][H * D * D];   // [which][hi/lo][h][dout][f]

// ---------------- helpers -------------------------------------------------------
__device__ __forceinline__ float ex2f(float x) {
    float y; asm("ex2.approx.ftz.f32 %0,%1;" : "=f"(y) : "f"(x)); return y;
}
#define CP16(d, s) asm volatile("cp.async.cg.shared.global [%0],[%1],16;" :: "r"(d), "l"(s) : "memory")
#define CPC()  asm volatile("cp.async.commit_group;" ::: "memory")
#define CPW0() asm volatile("cp.async.wait_group 0;" ::: "memory")
#define CPW1() asm volatile("cp.async.wait_group 1;" ::: "memory")

__device__ __forceinline__ uint32_t su32(const void* p) {
    return (uint32_t)__cvta_generic_to_shared(p);
}

__device__ __forceinline__ void mma(float* c, const uint32_t* a, uint32_t b0, uint32_t b1) {
    asm volatile(
        "mma.sync.aligned.m16n8k16.row.col.f32.f16.f16.f32 "
        "{%0,%1,%2,%3},{%4,%5,%6,%7},{%8,%9},{%0,%1,%2,%3};"
        : "+f"(c[0]), "+f"(c[1]), "+f"(c[2]), "+f"(c[3])
        : "r"(a[0]), "r"(a[1]), "r"(a[2]), "r"(a[3]), "r"(b0), "r"(b1));
}

__device__ __forceinline__ void pack2(float a, float b, uint32_t& hi, uint32_t& lo) {
    __half2 h = __floats2half2_rn(a, b);
    float2 f = __half22float2(h);
    __half2 r = __floats2half2_rn(a - f.x, b - f.y);
    hi = *(uint32_t*)&h; lo = *(uint32_t*)&r;
}

__device__ __forceinline__ uint32_t packhi(float a, float b) {
    __half2 h = __floats2half2_rn(a, b);
    return *(uint32_t*)&h;
}

// pack to fp16 pair AND accumulate the rounded-value sum (for consistent l)
__device__ __forceinline__ uint32_t packsum(float a, float b, float& acc) {
    __half2 h = __floats2half2_rn(a, b);
    float2 f = __half22float2(h);
    acc += f.x + f.y;
    return *(uint32_t*)&h;
}

// ================== attention smem: 2 stages of (Kh[64][136] | V[128][72]) ======
#define KST    17408
#define VST    18432
#define STG    (KST + VST)              // 35840
#define ASMEM  (2 * STG)                // 71680  -> 3 CTAs/SM

__device__ __forceinline__ void load_stage(uint32_t sb, int h, int kb, int tid, int slot) {
    size_t kof = (size_t)h * NT * D + (size_t)kb * BN * D;
    size_t vof = (size_t)h * D * NT + (size_t)kb * BN;
    uint32_t kbase = sb + (uint32_t)slot * STG;
    uint32_t vbase = kbase + KST;
    for (int c = tid; c < 1024; c += 128) {          // Kh: 64 rows x 16 chunks
        int r = c >> 4, k = c & 15;
        CP16(kbase + (uint32_t)(r * 272 + k * 16), g_kh + kof + (size_t)r * D + k * 8);
    }
    for (int c = tid; c < 1024; c += 128) {          // V: 128 dim-rows x 8 chunks
        int r = c >> 3, k = c & 7;
        CP16(vbase + (uint32_t)(r * 144 + k * 16), g_vh + vof + (size_t)r * NT + k * 8);
    }
}

__global__ void reset_ctr_kernel() { g_ctr = 0u; }

// ---------------- attention: persistent, split-K=4, 128 threads, 3 CTAs/SM ------
__global__ void __launch_bounds__(128, 3) attn_kernel() {
    extern __shared__ char sm[];
    __shared__ unsigned int sidx;
    const int tid = threadIdx.x, w = tid >> 5, l = tid & 31;
    const int lq = l >> 2, lr = l & 3;
    const uint32_t sb = su32(sm);
    const float L2E = 1.4426950408889634f;

    while (true) {
        if (tid == 0) sidx = atomicAdd(&g_ctr, 1u);
        __syncthreads();
        const unsigned int idx = sidx;
        if (idx >= NTILES) break;
        const int h  = (int)(idx >> 8);              // consecutive units share head
        const int q0 = (int)((idx >> 2) & 63) * 64;
        const int c  = (int)(idx & 3);               // key quarter
        const int kb0 = c * NBH;

        load_stage(sb, h, kb0, tid, 0); CPC();

        // Q fragments (fp16 hi only) — overlaps with async loads
        uint32_t qa[8][4];
        {
            const __half* qs = g_qh + ((size_t)h * NT + q0 + w * 16) * D;
#pragma unroll
            for (int j = 0; j < 8; j++) {
                const __half* base = qs + (size_t)lq * D + j * 16 + lr * 2;
                qa[j][0] = *(const uint32_t*)(base);
                qa[j][1] = *(const uint32_t*)(base + 8 * D);
                qa[j][2] = *(const uint32_t*)(base + 8);
                qa[j][3] = *(const uint32_t*)(base + 8 * D + 8);
            }
        }

        float o[16][4];
#pragma unroll
        for (int t = 0; t < 16; t++) { o[t][0] = o[t][1] = o[t][2] = o[t][3] = 0.f; }
        float m0 = -1e30f, m1 = -1e30f, l0 = 0.f, l1 = 0.f;

        for (int i = 0; i < NBH; i++) {
            __syncthreads();                 // all warps done reading slot (i+1)&1
            if (i + 1 < NBH) load_stage(sb, h, kb0 + i + 1, tid, (i + 1) & 1);
            CPC(); CPW1();                   // stage i complete
            __syncthreads();

            const char* stg = sm + (i & 1) * STG;
            const uint32_t* Kh32 = (const uint32_t*)(stg);
            const uint32_t* Vh32 = (const uint32_t*)(stg + KST);

            // ---- S = QhKh — single-term, accumulator-interleaved ----
            float s[8][4];
#pragma unroll
            for (int t = 0; t < 8; t++) { s[t][0] = s[t][1] = s[t][2] = s[t][3] = 0.f; }
#pragma unroll
            for (int j = 0; j < 8; j++) {
                uint32_t bh[8][2];
#pragma unroll
                for (int t = 0; t < 8; t++) {
                    int bi = (8 * t + lq) * 68 + j * 8 + lr;
                    bh[t][0] = Kh32[bi]; bh[t][1] = Kh32[bi + 4];
                }
#pragma unroll
                for (int t = 0; t < 8; t++) mma(s[t], qa[j], bh[t][0], bh[t][1]);
            }

            // ---- online softmax ----
            float rx0 = -1e30f, rx1 = -1e30f;
#pragma unroll
            for (int t = 0; t < 8; t++) {
                rx0 = fmaxf(rx0, fmaxf(s[t][0], s[t][1]));
                rx1 = fmaxf(rx1, fmaxf(s[t][2], s[t][3]));
            }
            rx0 = fmaxf(rx0, __shfl_xor_sync(~0u, rx0, 1));
            rx0 = fmaxf(rx0, __shfl_xor_sync(~0u, rx0, 2));
            rx1 = fmaxf(rx1, __shfl_xor_sync(~0u, rx1, 1));
            rx1 = fmaxf(rx1, __shfl_xor_sync(~0u, rx1, 2));
            float mn0 = fmaxf(m0, rx0), mn1 = fmaxf(m1, rx1);
            float sc0 = ex2f((m0 - mn0) * L2E), sc1 = ex2f((m1 - mn1) * L2E);
            m0 = mn0; m1 = mn1;
#pragma unroll
            for (int t = 0; t < 8; t++) {
                s[t][0] = ex2f((s[t][0] - mn0) * L2E);
                s[t][1] = ex2f((s[t][1] - mn0) * L2E);
                s[t][2] = ex2f((s[t][2] - mn1) * L2E);
                s[t][3] = ex2f((s[t][3] - mn1) * L2E);
            }

            // ---- pack P (fp16) and sum the ROUNDED values for l ----
            float rs0 = 0.f, rs1 = 0.f;
            uint32_t ph[4][4];
#pragma unroll
            for (int j = 0; j < 4; j++) {
                ph[j][0] = packsum(s[2 * j][0],     s[2 * j][1],     rs0);
                ph[j][1] = packsum(s[2 * j][2],     s[2 * j][3],     rs1);
                ph[j][2] = packsum(s[2 * j + 1][0], s[2 * j + 1][1], rs0);
                ph[j][3] = packsum(s[2 * j + 1][2], s[2 * j + 1][3], rs1);
            }
            rs0 += __shfl_xor_sync(~0u, rs0, 1); rs0 += __shfl_xor_sync(~0u, rs0, 2);
            rs1 += __shfl_xor_sync(~0u, rs1, 1); rs1 += __shfl_xor_sync(~0u, rs1, 2);
            l0 = l0 * sc0 + rs0; l1 = l1 * sc1 + rs1;
#pragma unroll
            for (int t = 0; t < 16; t++) {
                o[t][0] *= sc0; o[t][1] *= sc0; o[t][2] *= sc1; o[t][3] *= sc1;
            }

            // ---- O += PhVh — accumulator-interleaved sweep ----
#pragma unroll
            for (int j = 0; j < 4; j++) {
                uint32_t vb[16][2];
#pragma unroll
                for (int t = 0; t < 16; t++) {
                    int bi = (8 * t + lq) * 36 + j * 8 + lr;
                    vb[t][0] = Vh32[bi]; vb[t][1] = Vh32[bi + 4];
                }
#pragma unroll
                for (int t = 0; t < 16; t++) mma(o[t], ph[j], vb[t][0], vb[t][1]);
            }
        }

        // ---- epilogue: write UNNORMALIZED partials ----
        const int r0 = h * NT + q0 + w * 16 + lq;    // global row indices
        const int r1 = r0 + 8;
        float* po = g_po[c];
#pragma unroll
        for (int t = 0; t < 16; t++) {
            int col = 8 * t + lr * 2;
            *(float2*)(po + (size_t)r0 * D + col) = make_float2(o[t][0], o[t][1]);
            *(float2*)(po + (size_t)r1 * D + col) = make_float2(o[t][2], o[t][3]);
        }
        if (lr == 0) {
            g_pm[c][r0] = m0; g_pl[c][r0] = l0;
            g_pm[c][r1] = m1; g_pl[c][r1] = l1;
        }
        __syncthreads();   // smem reads done before next tile's prologue loads
    }
}

// ---------------- merge: combine key quarters exactly (fp32 LSE merge) ----------
// grid H*NT/8 = 4096, 256 threads: each warp merges one row, lane = 4 dims
__global__ void __launch_bounds__(256) merge_kernel(const float* __restrict__ W_m) {
    const int row = blockIdx.x * 8 + (threadIdx.x >> 5);
    const int lane = threadIdx.x & 31;
    const float L2E = 1.4426950408889634f;
    const int h = row >> 12;
    float m = -1e30f;
#pragma unroll
    for (int c = 0; c < SPLITK; c++) m = fmaxf(m, g_pm[c][row]);
    float e[SPLITK];
    float denom = 0.f;
#pragma unroll
    for (int c = 0; c < SPLITK; c++) {
        e[c] = ex2f((g_pm[c][row] - m) * L2E);
        denom += g_pl[c][row] * e[c];
    }
    float inv = W_m[h] / denom;
    size_t base = (size_t)row * D + lane * 4;
    float4 r = make_float4(0.f, 0.f, 0.f, 0.f);
#pragma unroll
    for (int c = 0; c < SPLITK; c++) {
        float s = e[c] * inv;
        float4 a = *(const float4*)(g_po[c] + base);
        r.x += a.x * s; r.y += a.y * s; r.z += a.z * s; r.w += a.w * s;
    }
    *(float4*)(g_o + base) = r;
}

// ================== prep: split x, split+transpose W ============================
__global__ void __launch_bounds__(256) splitx_kernel(const float* __restrict__ x) {
    int base = (blockIdx.x * 256 + threadIdx.x) * 8;
    float4 a = *(const float4*)(x + base);
    float4 b = *(const float4*)(x + base + 4);
    float v[8] = {a.x, a.y, a.z, a.w, b.x, b.y, b.z, b.w};
    __align__(16) __half hb[8], lb[8];
#pragma unroll
    for (int i = 0; i < 8; i++) {
        __half hh = __float2half_rn(v[i]);
        hb[i] = hh;
        lb[i] = __float2half_rn(v[i] - __half2float(hh));
    }
    *(uint4*)(g_xh + base) = *(uint4*)hb;
    *(uint4*)(g_xl + base) = *(uint4*)lb;
}

__global__ void __launch_bounds__(256) splitW_kernel(const float* __restrict__ Wk,
                                                     const float* __restrict__ Wq,
                                                     const float* __restrict__ Wv) {
    const int h = blockIdx.x, which = blockIdx.y;
    const float* W = (which == 0 ? Wq : which == 1 ? Wk : Wv) + (size_t)h * D * D;
    __half* oh = g_wT[which][0] + (size_t)h * D * D;
    __half* ol = g_wT[which][1] + (size_t)h * D * D;
    for (int idx = threadIdx.x; idx < D * D; idx += 256) {
        int dout = idx >> 7, f = idx & 127;
        float v = W[(size_t)f * D + dout];
        __half hh = __float2half_rn(v);
        oh[idx] = hh;
        ol[idx] = __float2half_rn(v - __half2float(hh));
    }
}

// ================== qkv via HMMA: grid (64, 8, 3), 128 threads, 3 CTAs/SM ======
#define WROW 136
#define QST  (128 * WROW * 2)
#define QSMEM (2 * QST)
#define TP 133

__global__ void __launch_bounds__(128, 3) qkv_mma_kernel() {
    extern __shared__ char sm[];
    const int tid = threadIdx.x, w = tid >> 5, l = tid & 31;
    const int tile = blockIdx.x, h = blockIdx.y, which = blockIdx.z;
    const int lq = l >> 2, lr = l & 3;
    const int n0 = tile * 64;

    {
        const uint32_t sb = su32(sm);
        const __half* wh = g_wT[which][0] + (size_t)h * D * D;
        const __half* wl = g_wT[which][1] + (size_t)h * D * D;
        for (int c = tid; c < 2048; c += 128) {
            int r = c >> 4, k = c & 15;
            uint32_t so = (uint32_t)(r * (WROW * 2) + k * 16);
            CP16(sb + so,       wh + (size_t)r * D + k * 8);
            CP16(sb + QST + so, wl + (size_t)r * D + k * 8);
        }
        CPC();
    }

    uint32_t xa[2][8][4];
#pragma unroll
    for (int s = 0; s < 2; s++) {
        const __half* xs = (s ? g_xl : g_xh) + (size_t)(n0 + w * 16) * D;
#pragma unroll
        for (int j = 0; j < 8; j++) {
            const __half* base = xs + (size_t)lq * D + j * 16 + lr * 2;
            xa[s][j][0] = *(const uint32_t*)(base);
            xa[s][j][1] = *(const uint32_t*)(base + 8 * D);
            xa[s][j][2] = *(const uint32_t*)(base + 8);
            xa[s][j][3] = *(const uint32_t*)(base + 8 * D + 8);
        }
    }

    CPW0();
    __syncthreads();

    const uint32_t* Wh32 = (const uint32_t*)(sm);
    const uint32_t* Wl32 = (const uint32_t*)(sm + QST);

    float s[16][4];
#pragma unroll
    for (int t = 0; t < 16; t++) { s[t][0] = s[t][1] = s[t][2] = s[t][3] = 0.f; }
#pragma unroll
    for (int j = 0; j < 8; j++) {
#pragma unroll
        for (int t = 0; t < 16; t++) {
            int bi = (8 * t + lq) * (WROW / 2) + j * 8 + lr;
            mma(s[t], xa[0][j], Wh32[bi], Wh32[bi + 4]);
        }
#pragma unroll
        for (int t = 0; t < 16; t++) {
            int bi = (8 * t + lq) * (WROW / 2) + j * 8 + lr;
            mma(s[t], xa[1][j], Wh32[bi], Wh32[bi + 4]);
        }
#pragma unroll
        for (int t = 0; t < 16; t++) {
            int bi = (8 * t + lq) * (WROW / 2) + j * 8 + lr;
            mma(s[t], xa[0][j], Wl32[bi], Wl32[bi + 4]);
        }
    }

    if (which < 2) {
        // q and k: fp16 hi only (both lo-terms dropped in attention)
        __half* oh = (which == 0 ? g_qh : g_kh) + ((size_t)h * NT + n0 + w * 16) * D;
#pragma unroll
        for (int t = 0; t < 16; t++) {
            int col = 8 * t + lr * 2;
            *(uint32_t*)(oh + (size_t)lq * D + col)       = packhi(s[t][0], s[t][1]);
            *(uint32_t*)(oh + (size_t)(lq + 8) * D + col) = packhi(s[t][2], s[t][3]);
        }
    } else {
        // v: transpose 64 rows via smem, store [h][d][n] fp16 coalesced
        __syncthreads();
        float* buf = (float*)sm;   // [64][TP]
#pragma unroll
        for (int t = 0; t < 16; t++) {
            int c = 8 * t + lr * 2;
            int r0 = w * 16 + lq, r1 = r0 + 8;
            buf[r0 * TP + c] = s[t][0]; buf[r0 * TP + c + 1] = s[t][1];
            buf[r1 * TP + c] = s[t][2]; buf[r1 * TP + c + 1] = s[t][3];
        }
        __syncthreads();
#pragma unroll
        for (int dd = 0; dd < 32; dd++) {
            int d = w * 32 + dd;
            int n2 = l * 2;
            __half hb[2];
            hb[0] = __float2half_rn(buf[n2 * TP + d]);
            hb[1] = __float2half_rn(buf[(n2 + 1) * TP + d]);
            *(uint32_t*)(g_vh + ((size_t)h * D + d) * NT + n0 + n2) = *(uint32_t*)hb;
        }
    }
}

// ---------------- Wg transpose + final MLP --------------------------------------
__global__ void wgT_kernel(const float* __restrict__ Wg) {
    int it = blockIdx.x * 256 + threadIdx.x;
    if (it < D * D) {
        int d = it >> 7, f = it & 127;
        g_wgT[f * D + d] = Wg[d * D + f];
    }
}

// grid 256 (16 rows per CTA), 256 threads
__global__ void __launch_bounds__(256) final_kernel(const float* __restrict__ x,
                                                    const float* __restrict__ bg,
                                                    float* __restrict__ y) {
    __shared__ float hs[16][132];
    __shared__ float Ws[16][132];
    __shared__ float bsh[D];
    const int n0 = blockIdx.x * 16;
    const int tid = threadIdx.x;

    for (int it = tid; it < 16 * 32; it += 256) {
        int r = it >> 5, c4 = it & 31;
        size_t off = (size_t)(n0 + r) * D + c4 * 4;
        float4 a = *(const float4*)(x + off);
#pragma unroll
        for (int hh = 0; hh < H; hh++) {
            float4 b = *(const float4*)(g_o + (size_t)hh * NT * D + off);
            a.x += b.x; a.y += b.y; a.z += b.z; a.w += b.w;
        }
        *(float4*)&hs[r][c4 * 4] = a;
    }
    if (tid < D) bsh[tid] = bg[tid];

    const int ty = tid >> 4, tx = tid & 15;
    float acc[8];
#pragma unroll
    for (int j = 0; j < 8; j++) acc[j] = 0.f;

    for (int fc = 0; fc < 8; fc++) {
        __syncthreads();
        for (int it = tid; it < 16 * 32; it += 256) {
            int r = it >> 5, c4 = it & 31;
            *(float4*)&Ws[r][c4 * 4] = *(const float4*)(g_wgT + (size_t)(fc * 16 + r) * D + c4 * 4);
        }
        __syncthreads();
#pragma unroll
        for (int f = 0; f < 16; f++) {
            float a = hs[ty][fc * 16 + f];
            float4 b0 = *(float4*)&Ws[f][tx * 8];
            float4 b1 = *(float4*)&Ws[f][tx * 8 + 4];
            acc[0] = fmaf(a, b0.x, acc[0]); acc[1] = fmaf(a, b0.y, acc[1]);
            acc[2] = fmaf(a, b0.z, acc[2]); acc[3] = fmaf(a, b0.w, acc[3]);
            acc[4] = fmaf(a, b1.x, acc[4]); acc[5] = fmaf(a, b1.y, acc[5]);
            acc[6] = fmaf(a, b1.z, acc[6]); acc[7] = fmaf(a, b1.w, acc[7]);
        }
    }

    {
        int n = n0 + ty;
#pragma unroll
        for (int jj = 0; jj < 8; jj += 4) {
            int d = tx * 8 + jj;
            float4 xv = *(const float4*)(x + (size_t)n * D + d);
            float4 r;
            r.x = xv.x + fmaxf(acc[jj + 0] + bsh[d + 0], 0.f);
            r.y = xv.y + fmaxf(acc[jj + 1] + bsh[d + 1], 0.f);
            r.z = xv.z + fmaxf(acc[jj + 2] + bsh[d + 2], 0.f);
            r.w = xv.w + fmaxf(acc[jj + 3] + bsh[d + 3], 0.f);
            *(float4*)(y + (size_t)n * D + d) = r;
        }
    }
}

// ---------------- launch ---------------------------------------------------------
extern "C" void kernel_launch(void* const* d_in, const int* in_sizes, int n_in,
                              void* d_out, int out_size) {
    const float* x  = (const float*)d_in[0];
    const float* Wk = (const float*)d_in[1];
    const float* Wq = (const float*)d_in[2];
    const float* Wv = (const float*)d_in[3];
    const float* Wm = (const float*)d_in[4];
    const float* Wg = (const float*)d_in[5];
    const float* bg = (const float*)d_in[6];
    float* y = (float*)d_out;

    cudaFuncSetAttribute(attn_kernel, cudaFuncAttributeMaxDynamicSharedMemorySize, ASMEM);
    cudaFuncSetAttribute(qkv_mma_kernel, cudaFuncAttributeMaxDynamicSharedMemorySize, QSMEM);

    reset_ctr_kernel<<<1, 1>>>();
    splitx_kernel<<<NT * D / (256 * 8), 256>>>(x);
    splitW_kernel<<<dim3(H, 3), 256>>>(Wk, Wq, Wv);
    wgT_kernel<<<(D * D + 255) / 256, 256>>>(Wg);
    qkv_mma_kernel<<<dim3(NT / 64, H, 3), 128, QSMEM>>>();
    attn_kernel<<<PGRID, 128, ASMEM>>>();
    merge_kernel<<<H * NT / 8, 256>>>(Wm);
    final_kernel<<<NT / 16, 256>>>(x, bg, y);
}